// round 17
// baseline (speedup 1.0000x reference)
#include <cuda_runtime.h>
#include <cstdint>
#include <cuda_bf16.h>
#include <cuda_fp16.h>
#include <mma.h>
using namespace nvcuda;

// Problem shape (fixed per dataset)
#define MAXN 50000
#define MAXE 800000
#define HH   128
#define GG   64
#define OO   64

// ---------------- scratch (static device globals; no allocs) ----------------
__device__ __align__(128) float          g_h   [MAXN * HH];
__device__ __align__(128) __half         g_hp16[MAXN * HH];
__device__ __align__(128) __nv_bfloat16  g_ahi [MAXN * HH];   // h as bf16 hi
__device__ __align__(128) __nv_bfloat16  g_alo [MAXN * HH];   // h as bf16 lo
__device__ __align__(128) __nv_bfloat16  g_whi [4 * HH * HH];
__device__ __align__(128) __nv_bfloat16  g_wlo [4 * HH * HH];
__device__ __align__(128) float          g_asp [4 * MAXN];
__device__ __align__(128) float          g_asum[2 * MAXN];
__device__ __align__(128) float          g_pool[GG * HH];
// CSR scratch
__device__ __align__(128) int g_counts[MAXN];
__device__ __align__(128) int g_part  [MAXN];
__device__ __align__(128) int g_rowptr[MAXN + 1];
__device__ __align__(128) int g_fillp [MAXN];
__device__ __align__(128) int g_bsum  [256];
__device__ __align__(128) int g_col   [MAXE + MAXN];
__device__ int g_is64;

// ---------------- helpers ----------------
__device__ __forceinline__ int ld_idx(const void* p, long i, int is64) {
    if (is64) return (int)((const long long*)p)[i];
    return ((const int*)p)[i];
}
__device__ __forceinline__ unsigned pack_bf(float a, float b) {
    __nv_bfloat162 v = __nv_bfloat162(__float2bfloat16(a), __float2bfloat16(b));
    return *(unsigned*)&v;
}

// ---------------- kernels ----------------

__global__ void k_zero_i(int* p, int n) {
    int i = blockIdx.x * blockDim.x + threadIdx.x;
    if (i < n) p[i] = 0;
}
__global__ void k_zero(float4* p, int n4) {
    int i = blockIdx.x * blockDim.x + threadIdx.x;
    if (i < n4) p[i] = make_float4(0.f, 0.f, 0.f, 0.f);
}

// split W0 + all Wl layers into bf16 hi/lo (once); thread 0 also detects
// int64 vs int32 indices.
__global__ void k_splitW(const float* __restrict__ W0, const float* __restrict__ Wl,
                         __nv_bfloat16* __restrict__ whi,
                         __nv_bfloat16* __restrict__ wlo, int L,
                         const unsigned long long* __restrict__ ei) {
    if (blockIdx.x == 0 && threadIdx.x == 0) {
        int is64 = 1;
        for (int i = 0; i < 64; i++)
            if (ei[i] > 1000000ull) is64 = 0;
        g_is64 = is64;
    }
    int i = blockIdx.x * blockDim.x + threadIdx.x;
    int total = (L + 1) * HH * HH;
    if (i >= total) return;
    float v = (i < HH * HH) ? W0[i] : Wl[i - HH * HH];
    __nv_bfloat16 h = __float2bfloat16(v);
    whi[i] = h;
    wlo[i] = __float2bfloat16(v - __bfloat162float(h));
}

// ---- CSR build ----
__global__ void k_hist(const void* ei, int* counts, int E, int n) {
    int e = blockIdx.x * blockDim.x + threadIdx.x;
    if (e >= E + n) return;
    int d = (e < E) ? ld_idx(ei, (long)E + e, g_is64) : (e - E);
    atomicAdd(&counts[d], 1);
}

__global__ __launch_bounds__(1024) void k_scanA(const int* counts, int* part,
                                                int* bsum, int n) {
    __shared__ int ws[32];
    int i = blockIdx.x * 1024 + threadIdx.x;
    int lane = threadIdx.x & 31, wid = threadIdx.x >> 5;
    int x = (i < n) ? counts[i] : 0;
#pragma unroll
    for (int o = 1; o < 32; o <<= 1) {
        int y = __shfl_up_sync(0xffffffffu, x, o);
        if (lane >= o) x += y;
    }
    if (lane == 31) ws[wid] = x;
    __syncthreads();
    if (wid == 0) {
        int y = ws[lane];
#pragma unroll
        for (int o = 1; o < 32; o <<= 1) {
            int z = __shfl_up_sync(0xffffffffu, y, o);
            if (lane >= o) y += z;
        }
        ws[lane] = y;
    }
    __syncthreads();
    int incl = x + (wid ? ws[wid - 1] : 0);
    if (i < n) part[i] = incl;
    if (threadIdx.x == 1023) bsum[blockIdx.x] = incl;
}

__global__ void k_scanC(const int* part, const int* bsum, const int* counts,
                        int* rowptr, int* fillp, int n) {
    __shared__ int pref;
    if (threadIdx.x == 0) {
        int target = blockIdx.x >> 2;
        int run = 0;
        for (int k = 0; k < target; k++) run += bsum[k];
        pref = run;
    }
    __syncthreads();
    int i = blockIdx.x * 256 + threadIdx.x;
    if (i == 0) rowptr[0] = 0;
    if (i < n) {
        int incl = part[i] + pref;
        rowptr[i + 1] = incl;
        fillp[i] = incl - counts[i];
    }
}
__global__ void k_fill(const void* ei, int* fillp, int* col, int E, int n) {
    int e = blockIdx.x * blockDim.x + threadIdx.x;
    if (e >= E + n) return;
    int is64 = g_is64;
    int s, d;
    if (e < E) { s = ld_idx(ei, e, is64); d = ld_idx(ei, (long)E + e, is64); }
    else       { s = d = e - E; }
    int pos = atomicAdd(&fillp[d], 1);
    col[pos] = s;
}

// bf16 split-compensated tensor-core GEMM. D = Ah@Wh + Ah@Wl + Al@Wh.
// 256 thr, block tile 128x64, 4 blocks/SM, 8 warps 4x2 (warp tile 32x32).
// A input: either fp32 (A, split fused into staging) or pre-split bf16
// (Ahi/Alo — staging = pure uint4 copies). Outputs: fp16 C16 and/or
// bf16 hi/lo (Chi/Clo) and/or alpha partials asp.
#define BLD 72
#define GEMM_SMEM ((2 * 128 * BLD + 2 * 64 * BLD) * (int)sizeof(__nv_bfloat16))
__global__ __launch_bounds__(256, 4) void k_gemm_bf(
    const float* __restrict__ A,
    const __nv_bfloat16* __restrict__ Ahi, const __nv_bfloat16* __restrict__ Alo,
    const __nv_bfloat16* __restrict__ Whi, const __nv_bfloat16* __restrict__ Wlo,
    const float* __restrict__ bias,
    const float* __restrict__ a_s, const float* __restrict__ a_d,
    float* __restrict__ asp,
    __half* __restrict__ C16,
    __nv_bfloat16* __restrict__ Chi, __nv_bfloat16* __restrict__ Clo,
    int nrows) {
    extern __shared__ __nv_bfloat16 smem[];
    __nv_bfloat16* sAh = smem;
    __nv_bfloat16* sAl = sAh + 128 * BLD;
    __nv_bfloat16* sWh = sAl + 128 * BLD;
    __nv_bfloat16* sWl = sWh + 64 * BLD;

    int t = threadIdx.x;
    int w = t >> 5;
    int wm = w >> 1, wn = w & 1;
    int row0 = blockIdx.x * 128;
    int col0 = blockIdx.y * 64;

    wmma::fragment<wmma::accumulator, 16, 16, 16, float> acc[2][2];
#pragma unroll
    for (int i = 0; i < 2; i++)
#pragma unroll
        for (int j = 0; j < 2; j++) wmma::fill_fragment(acc[i][j], 0.f);
    wmma::fragment<wmma::matrix_a, 16, 16, 16, __nv_bfloat16, wmma::row_major> ah[2], al[2];
    wmma::fragment<wmma::matrix_b, 16, 16, 16, __nv_bfloat16, wmma::row_major> bh, bl;

    for (int kc = 0; kc < HH; kc += 64) {
        if (Ahi) {
            // pre-split path: pure 16B copies (8 bf16 per uint4)
            const uint4 zz = make_uint4(0, 0, 0, 0);
            for (int i = t; i < 128 * 8; i += 256) {
                int r = i >> 3, c8 = (i & 7) << 3;
                uint4 vh = zz, vl = zz;
                if (row0 + r < nrows) {
                    vh = *(const uint4*)&Ahi[(long)(row0 + r) * HH + kc + c8];
                    vl = *(const uint4*)&Alo[(long)(row0 + r) * HH + kc + c8];
                }
                *(uint4*)&sAh[r * BLD + c8] = vh;
                *(uint4*)&sAl[r * BLD + c8] = vl;
            }
        } else {
            // fp32 path: split fused into staging
            for (int i = t; i < 128 * 16; i += 256) {
                int r = i >> 4, c4 = (i & 15) << 2;
                float4 a = make_float4(0.f, 0.f, 0.f, 0.f);
                if (row0 + r < nrows)
                    a = *(const float4*)&A[(long)(row0 + r) * HH + kc + c4];
                __nv_bfloat16 hx = __float2bfloat16(a.x);
                __nv_bfloat16 hy = __float2bfloat16(a.y);
                __nv_bfloat16 hz = __float2bfloat16(a.z);
                __nv_bfloat16 hw = __float2bfloat16(a.w);
                __nv_bfloat162 hv0 = __nv_bfloat162(hx, hy);
                __nv_bfloat162 hv1 = __nv_bfloat162(hz, hw);
                __nv_bfloat162 lv0 = __nv_bfloat162(
                    __float2bfloat16(a.x - __bfloat162float(hx)),
                    __float2bfloat16(a.y - __bfloat162float(hy)));
                __nv_bfloat162 lv1 = __nv_bfloat162(
                    __float2bfloat16(a.z - __bfloat162float(hz)),
                    __float2bfloat16(a.w - __bfloat162float(hw)));
                *(__nv_bfloat162*)&sAh[r * BLD + c4]     = hv0;
                *(__nv_bfloat162*)&sAh[r * BLD + c4 + 2] = hv1;
                *(__nv_bfloat162*)&sAl[r * BLD + c4]     = lv0;
                *(__nv_bfloat162*)&sAl[r * BLD + c4 + 2] = lv1;
            }
        }
        for (int i = t; i < 64 * 8; i += 256) {
            int r = i >> 3, c8 = (i & 7) << 3;
            *(uint4*)&sWh[r * BLD + c8] =
                *(const uint4*)&Whi[(long)(kc + r) * HH + col0 + c8];
            *(uint4*)&sWl[r * BLD + c8] =
                *(const uint4*)&Wlo[(long)(kc + r) * HH + col0 + c8];
        }
        __syncthreads();

#pragma unroll
        for (int kk = 0; kk < 64; kk += 16) {
#pragma unroll
            for (int i = 0; i < 2; i++) {
                wmma::load_matrix_sync(ah[i], &sAh[(wm * 32 + i * 16) * BLD + kk], BLD);
                wmma::load_matrix_sync(al[i], &sAl[(wm * 32 + i * 16) * BLD + kk], BLD);
            }
#pragma unroll
            for (int j = 0; j < 2; j++) {
                wmma::load_matrix_sync(bh, &sWh[kk * BLD + wn * 32 + j * 16], BLD);
                wmma::load_matrix_sync(bl, &sWl[kk * BLD + wn * 32 + j * 16], BLD);
#pragma unroll
                for (int i = 0; i < 2; i++) {
                    wmma::mma_sync(acc[i][j], ah[i], bh, acc[i][j]);
                    wmma::mma_sync(acc[i][j], ah[i], bl, acc[i][j]);
                    wmma::mma_sync(acc[i][j], al[i], bh, acc[i][j]);
                }
            }
        }
        __syncthreads();
    }

    float* sepi = (float*)smem;
#pragma unroll
    for (int i = 0; i < 2; i++)
#pragma unroll
        for (int j = 0; j < 2; j++)
            wmma::store_matrix_sync(&sepi[(wm * 32 + i * 16) * 68 + wn * 32 + j * 16],
                                    acc[i][j], 68, wmma::mem_row_major);
    __syncthreads();

    int r = t >> 1;
    int ch = (t & 1) * 32;
    int row = row0 + r;
    const float* srow = &sepi[r * 68 + ch];
    float ps = 0.f, pd = 0.f;
    float4 ov[8];
#pragma unroll
    for (int q = 0; q < 8; q++) {
        float4 v = make_float4(srow[q * 4], srow[q * 4 + 1],
                               srow[q * 4 + 2], srow[q * 4 + 3]);
        int c = col0 + ch + q * 4;
        if (bias) {
            v.x += bias[c]; v.y += bias[c + 1]; v.z += bias[c + 2]; v.w += bias[c + 3];
        }
        if (a_s) {
            ps += v.x * a_s[c] + v.y * a_s[c + 1] + v.z * a_s[c + 2] + v.w * a_s[c + 3];
            pd += v.x * a_d[c] + v.y * a_d[c + 1] + v.z * a_d[c + 2] + v.w * a_d[c + 3];
        }
        ov[q] = v;
    }
    if (a_s) {
        ps += __shfl_xor_sync(0xffffffffu, ps, 1);
        pd += __shfl_xor_sync(0xffffffffu, pd, 1);
    }
    if (row < nrows) {
        if (C16) {
#pragma unroll
            for (int q = 0; q < 8; q++) {
                __half2 ha = __floats2half2_rn(ov[q].x, ov[q].y);
                __half2 hb = __floats2half2_rn(ov[q].z, ov[q].w);
                uint2 pk;
                pk.x = *(unsigned*)&ha;
                pk.y = *(unsigned*)&hb;
                *(uint2*)&C16[(long)row * HH + col0 + ch + q * 4] = pk;
            }
        }
        if (Chi) {
#pragma unroll
            for (int q = 0; q < 8; q += 2) {
                uint4 vh, vl;
                float f[8] = {ov[q].x, ov[q].y, ov[q].z, ov[q].w,
                              ov[q + 1].x, ov[q + 1].y, ov[q + 1].z, ov[q + 1].w};
                float hi[8], lo[8];
#pragma unroll
                for (int u = 0; u < 8; u++) {
                    __nv_bfloat16 hb = __float2bfloat16(f[u]);
                    hi[u] = __bfloat162float(hb);
                    lo[u] = f[u] - hi[u];
                }
                vh.x = pack_bf(hi[0], hi[1]); vh.y = pack_bf(hi[2], hi[3]);
                vh.z = pack_bf(hi[4], hi[5]); vh.w = pack_bf(hi[6], hi[7]);
                vl.x = pack_bf(lo[0], lo[1]); vl.y = pack_bf(lo[2], lo[3]);
                vl.z = pack_bf(lo[4], lo[5]); vl.w = pack_bf(lo[6], lo[7]);
                *(uint4*)&Chi[(long)row * HH + col0 + ch + q * 4] = vh;
                *(uint4*)&Clo[(long)row * HH + col0 + ch + q * 4] = vl;
            }
        }
        if (a_s && (t & 1) == 0) {
            asp[row + blockIdx.y * nrows]             = ps;
            asp[row + 2 * nrows + blockIdx.y * nrows] = pd;
        }
    }
}

// combine the two col-block partials
__global__ void k_combine(const float* __restrict__ asp, float* __restrict__ asum,
                          int n) {
    int i = blockIdx.x * blockDim.x + threadIdx.x;
    if (i >= n) return;
    asum[i]     = asp[i] + asp[i + n];
    asum[i + n] = asp[i + 2 * n] + asp[i + 3 * n];
}

// warp per destination node; 32-lane score phase + 2-edges-per-LDG.128 gather.
// Output: bf16 hi/lo (relu layers, feeds next GEMM) or fp32 (last layer).
__global__ __launch_bounds__(256) void k_aggregate(
    const int* __restrict__ rowptr, const int* __restrict__ col,
    const float* __restrict__ asum,
    const __half* __restrict__ hp16, const float* __restrict__ bias,
    float* __restrict__ hout,
    __nv_bfloat16* __restrict__ hhi, __nv_bfloat16* __restrict__ hlo,
    int n, int relu) {
    int gid = blockIdx.x * blockDim.x + threadIdx.x;
    int w = gid >> 5, lane = gid & 31;
    if (w >= n) return;
    int half = lane >> 4, sub = lane & 15;
    int beg = rowptr[w], end = rowptr[w + 1];
    float add = __ldg(&asum[w + n]);

    float av[8] = {0.f, 0.f, 0.f, 0.f, 0.f, 0.f, 0.f, 0.f};
    float dl = 0.f;

    for (int base = beg; base < end; base += 32) {
        int cnt = min(32, end - base);
        int s = 0; float a = 0.f;
        if (lane < cnt) {
            s = __ldg(&col[base + lane]);
            float v = __ldg(&asum[s]) + add;
            v = v >= 0.f ? v : 0.2f * v;
            a = __expf(v);
        }
        dl += a;

        int t = 0;
#pragma unroll 1
        for (; t + 8 <= cnt; t += 8) {
            int st[4]; float at[4];
#pragma unroll
            for (int u = 0; u < 4; u++) {
                int idx = t + 2 * u + half;
                st[u] = __shfl_sync(0xffffffffu, s, idx);
                at[u] = __shfl_sync(0xffffffffu, a, idx);
            }
            uint4 uv[4];
#pragma unroll
            for (int u = 0; u < 4; u++)
                uv[u] = __ldg((const uint4*)(hp16 + (long)st[u] * HH) + sub);
#pragma unroll
            for (int u = 0; u < 4; u++) {
                __half2 p0 = *(__half2*)&uv[u].x, p1 = *(__half2*)&uv[u].y;
                __half2 p2 = *(__half2*)&uv[u].z, p3 = *(__half2*)&uv[u].w;
                float2 f0 = __half22float2(p0), f1 = __half22float2(p1);
                float2 f2 = __half22float2(p2), f3 = __half22float2(p3);
                av[0] = fmaf(at[u], f0.x, av[0]); av[1] = fmaf(at[u], f0.y, av[1]);
                av[2] = fmaf(at[u], f1.x, av[2]); av[3] = fmaf(at[u], f1.y, av[3]);
                av[4] = fmaf(at[u], f2.x, av[4]); av[5] = fmaf(at[u], f2.y, av[5]);
                av[6] = fmaf(at[u], f3.x, av[6]); av[7] = fmaf(at[u], f3.y, av[7]);
            }
        }
#pragma unroll 1
        for (; t < cnt; t += 2) {
            int idx = t + half;
            int pick = min(idx, cnt - 1);
            int   st = __shfl_sync(0xffffffffu, s, pick);
            float at = __shfl_sync(0xffffffffu, a, pick);
            if (idx >= cnt) at = 0.f;
            uint4 uv = __ldg((const uint4*)(hp16 + (long)st * HH) + sub);
            __half2 p0 = *(__half2*)&uv.x, p1 = *(__half2*)&uv.y;
            __half2 p2 = *(__half2*)&uv.z, p3 = *(__half2*)&uv.w;
            float2 f0 = __half22float2(p0), f1 = __half22float2(p1);
            float2 f2 = __half22float2(p2), f3 = __half22float2(p3);
            av[0] = fmaf(at, f0.x, av[0]); av[1] = fmaf(at, f0.y, av[1]);
            av[2] = fmaf(at, f1.x, av[2]); av[3] = fmaf(at, f1.y, av[3]);
            av[4] = fmaf(at, f2.x, av[4]); av[5] = fmaf(at, f2.y, av[5]);
            av[6] = fmaf(at, f3.x, av[6]); av[7] = fmaf(at, f3.y, av[7]);
        }
    }

#pragma unroll
    for (int k = 0; k < 8; k++)
        av[k] += __shfl_xor_sync(0xffffffffu, av[k], 16);
    float den = dl;
#pragma unroll
    for (int o = 16; o > 0; o >>= 1)
        den += __shfl_xor_sync(0xffffffffu, den, o);
    float inv = 1.f / den;

    if (half == 0) {
        float4 b0 = __ldg((const float4*)bias + sub * 2);
        float4 b1 = __ldg((const float4*)bias + sub * 2 + 1);
        float o[8];
        o[0] = fmaf(av[0], inv, b0.x); o[1] = fmaf(av[1], inv, b0.y);
        o[2] = fmaf(av[2], inv, b0.z); o[3] = fmaf(av[3], inv, b0.w);
        o[4] = fmaf(av[4], inv, b1.x); o[5] = fmaf(av[5], inv, b1.y);
        o[6] = fmaf(av[6], inv, b1.z); o[7] = fmaf(av[7], inv, b1.w);
        if (relu) {
#pragma unroll
            for (int k = 0; k < 8; k++) o[k] = fmaxf(o[k], 0.f);
            // emit bf16 hi/lo pair for the next GEMM
            uint4 vh, vl;
            float hi[8], lo[8];
#pragma unroll
            for (int k = 0; k < 8; k++) {
                __nv_bfloat16 hb = __float2bfloat16(o[k]);
                hi[k] = __bfloat162float(hb);
                lo[k] = o[k] - hi[k];
            }
            vh.x = pack_bf(hi[0], hi[1]); vh.y = pack_bf(hi[2], hi[3]);
            vh.z = pack_bf(hi[4], hi[5]); vh.w = pack_bf(hi[6], hi[7]);
            vl.x = pack_bf(lo[0], lo[1]); vl.y = pack_bf(lo[2], lo[3]);
            vl.z = pack_bf(lo[4], lo[5]); vl.w = pack_bf(lo[6], lo[7]);
            *(uint4*)&hhi[(long)w * HH + sub * 8] = vh;
            *(uint4*)&hlo[(long)w * HH + sub * 8] = vl;
        } else {
            *(float4*)&hout[(long)w * HH + sub * 8] =
                make_float4(o[0], o[1], o[2], o[3]);
            *(float4*)&hout[(long)w * HH + sub * 8 + 4] =
                make_float4(o[4], o[5], o[6], o[7]);
        }
    }
}

// global_add_pool over sorted batch
__global__ void k_pool(const float* __restrict__ h, const void* batch,
                       float* __restrict__ pool, int n) {
    __shared__ float s[GG * HH];
    for (int i = threadIdx.x; i < GG * HH; i += 256) s[i] = 0.f;
    __syncthreads();
    int is64 = g_is64;
    int per = (n + gridDim.x - 1) / gridDim.x;
    int i0 = blockIdx.x * per;
    int i1 = min(n, i0 + per);
    int c = threadIdx.x & 127, sub = threadIdx.x >> 7;
    float accv = 0.f; int curg = -1;
    for (int r = i0 + sub; r < i1; r += 2) {
        int g = ld_idx(batch, r, is64);
        if (g != curg) {
            if (curg >= 0) atomicAdd(&s[curg * HH + c], accv);
            accv = 0.f; curg = g;
        }
        accv += h[(long)r * HH + c];
    }
    if (curg >= 0) atomicAdd(&s[curg * HH + c], accv);
    __syncthreads();
    for (int i = threadIdx.x; i < GG * HH; i += 256) {
        float v = s[i];
        if (v != 0.f) atomicAdd(&pool[i], v);
    }
}

__global__ void k_final(const float* __restrict__ pool, const float* __restrict__ Wf,
                        const float* __restrict__ bf, float* __restrict__ out) {
    int i = blockIdx.x * blockDim.x + threadIdx.x;
    if (i >= GG * OO) return;
    int g = i >> 6, o = i & 63;
    float sa = bf[o];
#pragma unroll 8
    for (int k = 0; k < HH; k++) sa += pool[g * HH + k] * Wf[k * OO + o];
    out[i] = sa;
}

// ---------------- launch ----------------
extern "C" void kernel_launch(void* const* d_in, const int* in_sizes, int n_in,
                              void* d_out, int out_size) {
    const float* x     = (const float*)d_in[0];
    const void*  ei    = d_in[1];
    const void*  batch = d_in[2];
    const float* W0    = (const float*)d_in[3];
    const float* b0    = (const float*)d_in[4];
    const float* Wl    = (const float*)d_in[5];
    const float* a_src = (const float*)d_in[6];
    const float* a_dst = (const float*)d_in[7];
    const float* bl    = (const float*)d_in[8];
    const float* Wf    = (const float*)d_in[9];
    const float* bf    = (const float*)d_in[10];
    float* out = (float*)d_out;

    int n  = in_sizes[0] / HH;
    int E  = in_sizes[1] / 2;
    int et = E + n;
    int L  = in_sizes[5] / (HH * HH);

    float *h, *asp, *asum, *pool;
    __half* hp16;
    __nv_bfloat16 *ahi, *alo, *whi, *wlo;
    int *counts, *part, *rowptr, *fillp, *bsum, *col;
    cudaGetSymbolAddress((void**)&h,    g_h);
    cudaGetSymbolAddress((void**)&hp16, g_hp16);
    cudaGetSymbolAddress((void**)&ahi,  g_ahi);
    cudaGetSymbolAddress((void**)&alo,  g_alo);
    cudaGetSymbolAddress((void**)&whi,  g_whi);
    cudaGetSymbolAddress((void**)&wlo,  g_wlo);
    cudaGetSymbolAddress((void**)&asp,  g_asp);
    cudaGetSymbolAddress((void**)&asum, g_asum);
    cudaGetSymbolAddress((void**)&pool, g_pool);
    cudaGetSymbolAddress((void**)&counts, g_counts);
    cudaGetSymbolAddress((void**)&part,   g_part);
    cudaGetSymbolAddress((void**)&rowptr, g_rowptr);
    cudaGetSymbolAddress((void**)&fillp,  g_fillp);
    cudaGetSymbolAddress((void**)&bsum,   g_bsum);
    cudaGetSymbolAddress((void**)&col,    g_col);

    cudaFuncSetAttribute(k_gemm_bf, cudaFuncAttributeMaxDynamicSharedMemorySize,
                         GEMM_SMEM);

    dim3 tg((n + 127) / 128, 2);
    int nb = (n + 1023) / 1024;

    // slots 1-3 (slot 4 = k_gemm_bf profiled by ncu -s 5 -c 1)
    k_splitW<<<((L + 1) * HH * HH + 255) / 256, 256>>>(W0, Wl, whi, wlo, L,
                                                       (const unsigned long long*)ei);
    k_zero_i<<<(n + 255) / 256, 256>>>(counts, n);
    k_hist<<<(et + 255) / 256, 256>>>(ei, counts, E, n);

    // slot 4: gemm0 — h0 = x @ W0 + b0, emitted directly as bf16 hi/lo
    k_gemm_bf<<<tg, 256, GEMM_SMEM>>>(x, nullptr, nullptr, whi, wlo, b0,
                                      nullptr, nullptr, nullptr,
                                      nullptr, ahi, alo, n);

    // CSR rest
    k_scanA<<<nb, 1024>>>(counts, part, bsum, n);
    k_scanC<<<(n + 255) / 256, 256>>>(part, bsum, counts, rowptr, fillp, n);
    k_fill<<<(et + 255) / 256, 256>>>(ei, fillp, col, E, n);

    for (int l = 0; l < L; l++) {
        // layer GEMM: pre-split bf16 A, fp16 hp out + alpha partials
        k_gemm_bf<<<tg, 256, GEMM_SMEM>>>(nullptr, ahi, alo,
                                          whi + (long)(l + 1) * HH * HH,
                                          wlo + (long)(l + 1) * HH * HH, nullptr,
                                          a_src + l * HH, a_dst + l * HH,
                                          asp, hp16, nullptr, nullptr, n);
        k_combine<<<(n + 255) / 256, 256>>>(asp, asum, n);
        int relu = (l < L - 1) ? 1 : 0;
        k_aggregate<<<(n * 32 + 255) / 256, 256>>>(rowptr, col, asum, hp16,
                                                   bl + l * HH,
                                                   relu ? nullptr : h,
                                                   relu ? ahi : nullptr,
                                                   relu ? alo : nullptr,
                                                   n, relu);
    }

    k_zero<<<(GG * HH / 4 + 255) / 256, 256>>>((float4*)pool, GG * HH / 4);
    k_pool<<<128, 256>>>(h, batch, pool, n);
    k_final<<<(GG * OO + 255) / 256, 256>>>(pool, Wf, bf, out);
}